// round 10
// baseline (speedup 1.0000x reference)
#include <cuda_runtime.h>
#include <cuda_bf16.h>
#include <cuda_fp16.h>
#include <math.h>
#include <stdint.h>

// ---------------------------------------------------------------------------
// Problem constants
// ---------------------------------------------------------------------------
#define E_   4
#define N_   8192
#define DIN_ 1024
#define D_   512
#define L_   64
#define S_   128          // N_/L_
#define HID_ 1024
#define FF_  2048
#define M_   2
#define KK_  32
#define H_   8
#define DH_  64

#define INV_SD 0.04419417382415922f   // 1/sqrt(512)

// ---------------------------------------------------------------------------
// Scratch (static __device__ arrays; no allocation allowed)
// ---------------------------------------------------------------------------
static __device__ __align__(16) float g_KVb[(size_t)E_*N_*2*D_];    // fused [K|V], row stride 1024

// fp16 operand buffers
static __device__ __align__(16) __half g_xh [(size_t)E_*N_*DIN_];
static __device__ __align__(16) __half g_h1h[(size_t)E_*N_*HID_];
static __device__ __align__(16) __half g_fh [(size_t)E_*N_*D_];
static __device__ __align__(16) __half g_w1h[E_*DIN_*HID_];
static __device__ __align__(16) __half g_w2h[E_*HID_*D_];
static __device__ __align__(16) __half g_wkvh[E_*D_*2*D_];  // [K rows][2D cols]

static __device__ float g_q  [E_*L_*D_];
static __device__ float g_zo [E_*L_*D_];
static __device__ float g_tok[E_*L_*D_];
static __device__ float g_tn [E_*L_*D_];
static __device__ float g_xin[E_*L_*D_];
static __device__ float g_qkvb[E_*L_*3*D_];
static __device__ float g_ao [E_*L_*D_];
static __device__ float g_aop[E_*L_*D_];
static __device__ float g_x1 [E_*L_*D_];
static __device__ float g_ffh[E_*L_*FF_];
static __device__ float g_ffo[E_*L_*D_];
static __device__ float g_eo [E_*L_*D_];
static __device__ float g_retr[E_*L_*M_*D_];
static __device__ float g_eout[E_*L_*D_];
static __device__ float g_pooled[E_*D_];
static __device__ float g_gw[E_];

// ---------------------------------------------------------------------------
// Reduction helpers
// ---------------------------------------------------------------------------
__device__ __forceinline__ float warp_sum(float v) {
    #pragma unroll
    for (int o = 16; o; o >>= 1) v += __shfl_xor_sync(0xffffffffu, v, o);
    return v;
}
__device__ __forceinline__ float warp_max(float v) {
    #pragma unroll
    for (int o = 16; o; o >>= 1) v = fmaxf(v, __shfl_xor_sync(0xffffffffu, v, o));
    return v;
}
__device__ __forceinline__ float block_sum128(float v, float* sh) {
    int lane = threadIdx.x & 31, w = threadIdx.x >> 5;
    v = warp_sum(v);
    if (lane == 0) sh[w] = v;
    __syncthreads();
    float r = sh[0] + sh[1] + sh[2] + sh[3];
    __syncthreads();
    return r;
}
__device__ __forceinline__ float clip5(float x) {
    return fminf(fmaxf(x, -5.0f), 5.0f);
}

// ---------------------------------------------------------------------------
// Tensor-core primitives (legacy mma.sync path — tcgen05 unavailable at the
// harness's ptxas target sm_100)
// ---------------------------------------------------------------------------
__device__ __forceinline__ uint32_t smem_u32(const void* p) {
    return (uint32_t)__cvta_generic_to_shared(p);
}
__device__ __forceinline__ void cpa16(void* dst, const void* src) {
    uint32_t d = smem_u32(dst);
    asm volatile("cp.async.cg.shared.global [%0], [%1], 16;\n" :: "r"(d), "l"(src));
}
__device__ __forceinline__ void ldsm4(uint32_t* r, uint32_t addr) {
    asm volatile("ldmatrix.sync.aligned.m8n8.x4.shared.b16 {%0,%1,%2,%3}, [%4];\n"
                 : "=r"(r[0]), "=r"(r[1]), "=r"(r[2]), "=r"(r[3]) : "r"(addr));
}
__device__ __forceinline__ void ldsm4t(uint32_t* r, uint32_t addr) {
    asm volatile("ldmatrix.sync.aligned.m8n8.x4.trans.shared.b16 {%0,%1,%2,%3}, [%4];\n"
                 : "=r"(r[0]), "=r"(r[1]), "=r"(r[2]), "=r"(r[3]) : "r"(addr));
}
__device__ __forceinline__ void mma16816h(float* c, const uint32_t* a, const uint32_t* b) {
    asm volatile(
        "mma.sync.aligned.m16n8k16.row.col.f32.f16.f16.f32 "
        "{%0,%1,%2,%3}, {%4,%5,%6,%7}, {%8,%9}, {%0,%1,%2,%3};\n"
        : "+f"(c[0]), "+f"(c[1]), "+f"(c[2]), "+f"(c[3])
        : "r"(a[0]), "r"(a[1]), "r"(a[2]), "r"(a[3]), "r"(b[0]), "r"(b[1]));
}

// smem geometry: A fp16 (128x32, stride 40), B fp16 (32x128, stride 136)
#define A_STRIDE 40
#define B_STRIDE 136
#define SA_ELEMS (128 * A_STRIDE)       // 5120
#define SB_ELEMS (32 * B_STRIDE)        // 4352
#define STAGE_ELEMS (SA_ELEMS + SB_ELEMS)           // 9472 half
#define STAGES 4
#define GEMM_SMEM_BYTES (STAGES * STAGE_ELEMS * 2)  // 75776 B

__device__ __forceinline__ void gemm_prefetch(
    __half* s,
    const __half* __restrict__ A, const __half* __restrict__ B,
    int m0, int n0, int k0, int Ktot, int Ntot, int tid)
{
    __half* sA = s;
    __half* sB = s + SA_ELEMS;
    const int ar = tid >> 2, akc = (tid & 3) * 8;
    cpa16(sA + ar * A_STRIDE + akc, A + (size_t)(m0 + ar) * Ktot + k0 + akc);
    const int br = tid >> 4, bnc = (tid & 15) * 8;
    cpa16(sB + br * B_STRIDE + bnc, B + (size_t)(k0 + br) * Ntot + n0 + bnc);
}

// C[e] = act(A[e] @ B[e] + bias[e]); A,B fp16, fp32 accumulate.
// BM=BN=128, BK=32, 512 threads (16 warps, 4x4 grid, warp tile 32x32).
template<bool RELU, bool HAS_BIAS, bool OUT_HALF>
__global__ void __launch_bounds__(512, 1)
mma_gemm(const __half* __restrict__ A, const __half* __restrict__ B,
         const float* __restrict__ bias,
         float* __restrict__ Cf, __half* __restrict__ Ch,
         int Mtot, int Ntot, int Ktot)
{
    extern __shared__ __half sm[];
    const int e = blockIdx.z;
    A += (size_t)e * Mtot * Ktot;
    B += (size_t)e * Ktot * Ntot;
    if (HAS_BIAS) bias += (size_t)e * Ntot;
    if (OUT_HALF) Ch += (size_t)e * Mtot * Ntot;
    else          Cf += (size_t)e * Mtot * Ntot;

    const int m0 = blockIdx.y * 128, n0 = blockIdx.x * 128;
    const int tid = threadIdx.x, lane = tid & 31, warp = tid >> 5;
    const int wm = warp & 3, wn = warp >> 2;

    float acc[2][4][4];
    #pragma unroll
    for (int mi = 0; mi < 2; ++mi)
        #pragma unroll
        for (int ni = 0; ni < 4; ++ni)
            #pragma unroll
            for (int r = 0; r < 4; ++r) acc[mi][ni][r] = 0.f;

    const int nk = Ktot / 32;

    #pragma unroll
    for (int s = 0; s < STAGES - 1; ++s) {
        if (s < nk)
            gemm_prefetch(sm + s * STAGE_ELEMS, A, B, m0, n0, s * 32, Ktot, Ntot, tid);
        asm volatile("cp.async.commit_group;\n" ::: "memory");
    }

    for (int kt = 0; kt < nk; ++kt) {
        asm volatile("cp.async.wait_group %0;\n" :: "n"(STAGES - 2) : "memory");
        __syncthreads();

        const int pf = kt + STAGES - 1;
        if (pf < nk)
            gemm_prefetch(sm + (pf % STAGES) * STAGE_ELEMS, A, B,
                          m0, n0, pf * 32, Ktot, Ntot, tid);
        asm volatile("cp.async.commit_group;\n" ::: "memory");

        const __half* s = sm + (kt % STAGES) * STAGE_ELEMS;
        const uint32_t sbase = smem_u32(s);
        const uint32_t aB = sbase + (uint32_t)(((wm * 32 + (lane & 15)) * A_STRIDE
                                               + (lane >> 4) * 8) * 2);
        const uint32_t bB = sbase + (uint32_t)((SA_ELEMS
                            + ((lane & 7) + ((lane >> 3) & 1) * 8) * B_STRIDE
                            + wn * 32 + (lane >> 4) * 8) * 2);

        #pragma unroll
        for (int ks = 0; ks < 2; ++ks) {
            uint32_t a[2][4], b[4][2];
            #pragma unroll
            for (int mi = 0; mi < 2; ++mi)
                ldsm4(a[mi], aB + ks * 32 + mi * (16 * A_STRIDE * 2));
            #pragma unroll
            for (int pr = 0; pr < 2; ++pr) {
                uint32_t r[4];
                ldsm4t(r, bB + ks * (16 * B_STRIDE * 2) + pr * 32);
                b[2*pr][0] = r[0]; b[2*pr][1] = r[1];
                b[2*pr+1][0] = r[2]; b[2*pr+1][1] = r[3];
            }
            #pragma unroll
            for (int mi = 0; mi < 2; ++mi)
                #pragma unroll
                for (int ni = 0; ni < 4; ++ni)
                    mma16816h(acc[mi][ni], a[mi], b[ni]);
        }
    }

    const int g  = lane >> 2;
    const int c2 = (lane & 3) * 2;
    #pragma unroll
    for (int mi = 0; mi < 2; ++mi) {
        const int r0 = m0 + wm * 32 + mi * 16 + g;
        #pragma unroll
        for (int ni = 0; ni < 4; ++ni) {
            const int col = n0 + wn * 32 + ni * 8 + c2;
            float bx = 0.f, by = 0.f;
            if (HAS_BIAS) { float2 bb = *(const float2*)&bias[col]; bx = bb.x; by = bb.y; }
            float v00 = acc[mi][ni][0] + bx, v01 = acc[mi][ni][1] + by;
            float v10 = acc[mi][ni][2] + bx, v11 = acc[mi][ni][3] + by;
            if (RELU) {
                v00 = fmaxf(v00, 0.f); v01 = fmaxf(v01, 0.f);
                v10 = fmaxf(v10, 0.f); v11 = fmaxf(v11, 0.f);
            }
            if (OUT_HALF) {
                __half2 h0; h0.x = __float2half_rn(v00); h0.y = __float2half_rn(v01);
                __half2 h1; h1.x = __float2half_rn(v10); h1.y = __float2half_rn(v11);
                *(__half2*)(Ch + (size_t)r0 * Ntot + col)       = h0;
                *(__half2*)(Ch + (size_t)(r0 + 8) * Ntot + col) = h1;
            } else {
                float2 o0; o0.x = v00; o0.y = v01;
                float2 o1; o1.x = v10; o1.y = v11;
                *(float2*)&Cf[(size_t)r0 * Ntot + col]       = o0;
                *(float2*)&Cf[(size_t)(r0 + 8) * Ntot + col] = o1;
            }
        }
    }
}

// ---------------------------------------------------------------------------
// Fused GEMM2 + double-LayerNorm + fp16 write:
// f = LN( LN(h1 @ w2 + b2) * g + bt )  -> g_fh
// BM=32, BN=512(full), BK=32, 512 threads, 16 warps (2m x 8n), warp tile 16x64
// ---------------------------------------------------------------------------
#define B2_STRIDE 520
#define SA2_ELEMS (32 * A_STRIDE)                       // 1280
#define SB2_ELEMS (32 * B2_STRIDE)                      // 16640
#define STAGE2_ELEMS (SA2_ELEMS + SB2_ELEMS)            // 17920 half
#define G2_SMEM_BYTES (STAGES * STAGE2_ELEMS * 2)       // 143360 B

__device__ __forceinline__ void g2_prefetch(
    __half* s, const __half* __restrict__ A, const __half* __restrict__ B,
    int m0, int k0, int tid)
{
    __half* sA = s;
    __half* sB = s + SA2_ELEMS;
    if (tid < 128) {
        const int ar = tid >> 2, akc = (tid & 3) * 8;
        cpa16(sA + ar * A_STRIDE + akc, A + (size_t)(m0 + ar) * HID_ + k0 + akc);
    }
    #pragma unroll
    for (int j = 0; j < 4; ++j) {
        const int c = tid + j * 512;
        const int br = c >> 6, bnc = (c & 63) * 8;
        cpa16(sB + br * B2_STRIDE + bnc, B + (size_t)(k0 + br) * D_ + bnc);
    }
}

__global__ void __launch_bounds__(512, 1)
gemm2_ln_kernel(const __half* __restrict__ A, const __half* __restrict__ B,
                const float* __restrict__ bias,
                const float* __restrict__ gg, const float* __restrict__ bt)
{
    extern __shared__ __half sm[];
    const int e = blockIdx.z;
    A    += (size_t)e * N_ * HID_;
    B    += (size_t)e * HID_ * D_;
    bias += (size_t)e * D_;
    gg   += (size_t)e * D_;
    bt   += (size_t)e * D_;
    __half* fo = g_fh + (size_t)e * N_ * D_;

    const int m0 = blockIdx.x * 32;
    const int tid = threadIdx.x, lane = tid & 31, warp = tid >> 5;
    const int wm = warp & 1, wn = warp >> 1;    // 2 x 8 warp grid, tile 16x64

    float acc[8][4];
    #pragma unroll
    for (int ni = 0; ni < 8; ++ni)
        #pragma unroll
        for (int r = 0; r < 4; ++r) acc[ni][r] = 0.f;

    const int nk = HID_ / 32;   // 32

    #pragma unroll
    for (int s = 0; s < STAGES - 1; ++s) {
        g2_prefetch(sm + s * STAGE2_ELEMS, A, B, m0, s * 32, tid);
        asm volatile("cp.async.commit_group;\n" ::: "memory");
    }

    for (int kt = 0; kt < nk; ++kt) {
        asm volatile("cp.async.wait_group %0;\n" :: "n"(STAGES - 2) : "memory");
        __syncthreads();

        const int pf = kt + STAGES - 1;
        if (pf < nk)
            g2_prefetch(sm + (pf % STAGES) * STAGE2_ELEMS, A, B, m0, pf * 32, tid);
        asm volatile("cp.async.commit_group;\n" ::: "memory");

        const __half* s = sm + (kt % STAGES) * STAGE2_ELEMS;
        const uint32_t sbase = smem_u32(s);
        const uint32_t aB = sbase + (uint32_t)(((wm * 16 + (lane & 15)) * A_STRIDE
                                               + (lane >> 4) * 8) * 2);
        const uint32_t bB = sbase + (uint32_t)((SA2_ELEMS
                            + ((lane & 7) + ((lane >> 3) & 1) * 8) * B2_STRIDE
                            + wn * 64 + (lane >> 4) * 8) * 2);

        #pragma unroll
        for (int ks = 0; ks < 2; ++ks) {
            uint32_t a[4], b[8][2];
            ldsm4(a, aB + ks * 32);
            #pragma unroll
            for (int pr = 0; pr < 4; ++pr) {
                uint32_t r[4];
                ldsm4t(r, bB + ks * (16 * B2_STRIDE * 2) + pr * 32);
                b[2*pr][0] = r[0]; b[2*pr][1] = r[1];
                b[2*pr+1][0] = r[2]; b[2*pr+1][1] = r[3];
            }
            #pragma unroll
            for (int ni = 0; ni < 8; ++ni)
                mma16816h(acc[ni], a, b[ni]);
        }
    }

    // drain async, then reuse smem as fp32 staging (32 x 520)
    asm volatile("cp.async.wait_group 0;\n" ::: "memory");
    __syncthreads();
    float* Cs = (float*)sm;

    const int g  = lane >> 2;
    const int c2 = (lane & 3) * 2;
    #pragma unroll
    for (int ni = 0; ni < 8; ++ni) {
        const int col = wn * 64 + ni * 8 + c2;
        const float2 bb = *(const float2*)&bias[col];
        Cs[(wm * 16 + g    ) * 520 + col    ] = acc[ni][0] + bb.x;
        Cs[(wm * 16 + g    ) * 520 + col + 1] = acc[ni][1] + bb.y;
        Cs[(wm * 16 + g + 8) * 520 + col    ] = acc[ni][2] + bb.x;
        Cs[(wm * 16 + g + 8) * 520 + col + 1] = acc[ni][3] + bb.y;
    }
    __syncthreads();

    // double-LN: each warp handles 2 rows (lane holds 16 strided elems)
    #pragma unroll
    for (int rr = 0; rr < 2; ++rr) {
        const int row = warp * 2 + rr;
        float v[16];
        #pragma unroll
        for (int i = 0; i < 16; ++i) v[i] = Cs[row * 520 + lane + 32 * i];
        float s = 0.f;
        #pragma unroll
        for (int i = 0; i < 16; ++i) s += v[i];
        s = warp_sum(s);
        float mu = s * (1.f / 512.f);
        float q = 0.f;
        #pragma unroll
        for (int i = 0; i < 16; ++i) { float d = v[i] - mu; q += d * d; }
        q = warp_sum(q);
        float rs = rsqrtf(q * (1.f / 512.f) + 1e-5f);
        #pragma unroll
        for (int i = 0; i < 16; ++i)
            v[i] = (v[i] - mu) * rs * gg[lane + 32 * i] + bt[lane + 32 * i];
        s = 0.f;
        #pragma unroll
        for (int i = 0; i < 16; ++i) s += v[i];
        s = warp_sum(s);
        mu = s * (1.f / 512.f);
        q = 0.f;
        #pragma unroll
        for (int i = 0; i < 16; ++i) { float d = v[i] - mu; q += d * d; }
        q = warp_sum(q);
        rs = rsqrtf(q * (1.f / 512.f) + 1e-5f);
        #pragma unroll
        for (int i = 0; i < 16; ++i)
            fo[(size_t)(m0 + row) * 512 + lane + 32 * i] =
                __float2half_rn((v[i] - mu) * rs);
    }
}

// fp32 -> fp16 (grid-stride)
__global__ void __launch_bounds__(256)
tohalf_kernel(const float* __restrict__ in, __half* __restrict__ out, int n4)
{
    for (int i = blockIdx.x * 256 + threadIdx.x; i < n4; i += gridDim.x * 256) {
        const float4 v = ((const float4*)in)[i];
        __half2 h0, h1;
        h0.x = __float2half_rn(v.x); h0.y = __float2half_rn(v.y);
        h1.x = __float2half_rn(v.z); h1.y = __float2half_rn(v.w);
        __half2* op = (__half2*)(out + 4 * (size_t)i);
        op[0] = h0; op[1] = h1;
    }
}

// pack wk|wv -> [E][D rows (k)][1024 cols] fp16 (grid-stride)
__global__ void __launch_bounds__(256)
pack_kv_h(const float* __restrict__ wk, const float* __restrict__ wv,
          __half* __restrict__ out)
{
    const int n4 = E_ * D_ * 2 * D_ / 4;
    for (int i = blockIdx.x * 256 + threadIdx.x; i < n4; i += gridDim.x * 256) {
        const int idx4 = i * 4;
        const int e   = idx4 / (D_ * 2 * D_);
        const int rem = idx4 % (D_ * 2 * D_);
        const int r   = rem / (2 * D_);
        const int c   = rem % (2 * D_);
        const float* src = (c < D_)
            ? (wk + ((size_t)e * D_ + r) * D_ + c)
            : (wv + ((size_t)e * D_ + r) * D_ + (c - D_));
        const float4 v = *(const float4*)src;
        __half2 h0, h1;
        h0.x = __float2half_rn(v.x); h0.y = __float2half_rn(v.y);
        h1.x = __float2half_rn(v.z); h1.y = __float2half_rn(v.w);
        __half2* op = (__half2*)(out + idx4);
        op[0] = h0; op[1] = h1;
    }
}

// ---------------------------------------------------------------------------
// Small GEMM: M=64 rows, 64-wide N tiles, BK=16, 256 thr, 4x4 per thread
// ---------------------------------------------------------------------------
template<bool RELU, bool HAS_BIAS, bool RESID>
__global__ void __launch_bounds__(256)
small_gemm_kernel(const float* __restrict__ A, const float* __restrict__ B,
                  const float* __restrict__ bias, const float* __restrict__ resid,
                  float* __restrict__ C, int Ntot, int Ktot,
                  long long sA, long long sB, long long sBias, long long sC)
{
    const int e = blockIdx.z;
    A += (size_t)e * sA;
    B += (size_t)e * sB;
    C += (size_t)e * sC;
    if (HAS_BIAS) bias += (size_t)e * sBias;
    if (RESID)    resid += (size_t)e * sC;

    __shared__ float As[16][64];
    __shared__ float Bs[16][68];

    const int tid   = threadIdx.x;
    const int n0    = blockIdx.x * 64;
    const int arow  = tid >> 2;
    const int acol4 = (tid & 3) * 4;
    const int brow  = tid >> 4;
    const int bcol4 = (tid & 15) * 4;
    const int tr    = (tid >> 4) * 4;
    const int tc    = (tid & 15) * 4;

    float acc[4][4];
    #pragma unroll
    for (int i = 0; i < 4; i++)
        #pragma unroll
        for (int j = 0; j < 4; j++) acc[i][j] = 0.f;

    const float* Ap = A + (size_t)arow * Ktot + acol4;
    const float* Bp = B + (size_t)brow * Ntot + n0 + bcol4;

    for (int k0 = 0; k0 < Ktot; k0 += 16) {
        float4 a4 = *(const float4*)Ap;
        float4 b4 = *(const float4*)Bp;
        As[acol4 + 0][arow] = a4.x;
        As[acol4 + 1][arow] = a4.y;
        As[acol4 + 2][arow] = a4.z;
        As[acol4 + 3][arow] = a4.w;
        *(float4*)&Bs[brow][bcol4] = b4;
        __syncthreads();
        #pragma unroll
        for (int k = 0; k < 16; ++k) {
            float ar[4], br[4];
            #pragma unroll
            for (int i = 0; i < 4; ++i) ar[i] = As[k][tr + i];
            #pragma unroll
            for (int j = 0; j < 4; ++j) br[j] = Bs[k][tc + j];
            #pragma unroll
            for (int i = 0; i < 4; ++i)
                #pragma unroll
                for (int j = 0; j < 4; ++j)
                    acc[i][j] = fmaf(ar[i], br[j], acc[i][j]);
        }
        __syncthreads();
        Ap += 16;
        Bp += (size_t)16 * Ntot;
    }

    #pragma unroll
    for (int i = 0; i < 4; ++i) {
        const int row = tr + i;
        float* cp = C + (size_t)row * Ntot + n0 + tc;
        #pragma unroll
        for (int j = 0; j < 4; ++j) {
            float o = acc[i][j];
            if (HAS_BIAS) o += bias[n0 + tc + j];
            if (RESID)    o += resid[(size_t)row * Ntot + n0 + tc + j];
            if (RELU)     o = fmaxf(o, 0.f);
            cp[j] = o;
        }
    }
}

// ---------------------------------------------------------------------------
// LayerNorm over D=512, 128 threads/row: out = LN(in [+ res]) [* g + b]
// ---------------------------------------------------------------------------
template<bool RES, bool AFF>
__global__ void __launch_bounds__(128)
ln_kernel(const float* __restrict__ in, const float* __restrict__ res,
          const float* __restrict__ gg, const float* __restrict__ bb,
          float* __restrict__ out, int rowsPerE)
{
    __shared__ float sh[4];
    const int row = blockIdx.x;
    const int e   = row / rowsPerE;
    const int t   = threadIdx.x;
    const float* ip = in + (size_t)row * 512;

    float v[4];
    #pragma unroll
    for (int i = 0; i < 4; ++i) {
        v[i] = ip[t + 128 * i];
        if (RES) v[i] += res[(size_t)row * 512 + t + 128 * i];
    }
    float s = block_sum128(v[0] + v[1] + v[2] + v[3], sh);
    const float mu = s * (1.f / 512.f);
    float q = 0.f;
    #pragma unroll
    for (int i = 0; i < 4; ++i) { float d = v[i] - mu; q += d * d; }
    q = block_sum128(q, sh);
    const float rs = rsqrtf(q * (1.f / 512.f) + 1e-5f);
    #pragma unroll
    for (int i = 0; i < 4; ++i) {
        float o = (v[i] - mu) * rs;
        if (AFF) o = o * gg[e * 512 + t + 128 * i] + bb[e * 512 + t + 128 * i];
        out[(size_t)row * 512 + t + 128 * i] = o;
    }
}

// ---------------------------------------------------------------------------
// LSTCWA segment cross-attention (reads fused [K|V] buffer, row stride 1024)
// ---------------------------------------------------------------------------
__global__ void __launch_bounds__(128)
lstcwa_kernel()
{
    __shared__ float qs[512];
    __shared__ float sc[128];
    __shared__ float sh[4];
    const int e = blockIdx.x >> 6, l = blockIdx.x & 63;
    const int t = threadIdx.x, lane = t & 31, warp = t >> 5;

    const float* qrow = g_q + ((size_t)e * L_ + l) * 512;
    #pragma unroll
    for (int i = t; i < 512; i += 128) qs[i] = qrow[i];
    __syncthreads();

    const float* kvbase = g_KVb + ((size_t)e * N_ + (size_t)l * S_) * 1024;
    for (int s = warp; s < 128; s += 4) {
        const float* kr = kvbase + (size_t)s * 1024;
        float p = 0.f;
        #pragma unroll
        for (int i = 0; i < 16; ++i) p = fmaf(kr[lane + 32 * i], qs[lane + 32 * i], p);
        p = warp_sum(p);
        if (lane == 0) sc[s] = clip5(p * INV_SD);
    }
    __syncthreads();

    float v = sc[t];
    float m = warp_max(v);
    if (lane == 0) sh[warp] = m;
    __syncthreads();
    m = fmaxf(fmaxf(sh[0], sh[1]), fmaxf(sh[2], sh[3]));
    __syncthreads();
    float ex = expf(v - m);
    float s1 = warp_sum(ex);
    if (lane == 0) sh[warp] = s1;
    __syncthreads();
    const float inv = 1.f / (sh[0] + sh[1] + sh[2] + sh[3]);
    sc[t] = ex * inv;
    __syncthreads();

    const float* vbase = kvbase + 512;
    float acc[4] = {0.f, 0.f, 0.f, 0.f};
    for (int s = 0; s < 128; ++s) {
        const float w = sc[s];
        const float* vr = vbase + (size_t)s * 1024;
        #pragma unroll
        for (int i = 0; i < 4; ++i) acc[i] = fmaf(w, vr[t + 128 * i], acc[i]);
    }
    float* zo = g_zo + ((size_t)e * L_ + l) * 512;
    #pragma unroll
    for (int i = 0; i < 4; ++i) zo[t + 128 * i] = acc[i];
}

// ---------------------------------------------------------------------------
// Cross-backbone attention
// ---------------------------------------------------------------------------
__global__ void __launch_bounds__(128)
crossattn_kernel()
{
    __shared__ float qs[512];
    __shared__ float sc[64];
    __shared__ float sh[4];
    const int e = blockIdx.x >> 6, l = blockIdx.x & 63;
    const int ce = (e == 0) ? 1 : 0;
    const int t = threadIdx.x, lane = t & 31, warp = t >> 5;

    const float* qrow = g_tn + ((size_t)e * L_ + l) * 512;
    #pragma unroll
    for (int i = t; i < 512; i += 128) qs[i] = qrow[i];
    __syncthreads();

    const float* kbase = g_tn + (size_t)ce * L_ * 512;
    for (int s = warp; s < 64; s += 4) {
        const float* kr = kbase + (size_t)s * 512;
        float p = 0.f;
        #pragma unroll
        for (int i = 0; i < 16; ++i) p = fmaf(kr[lane + 32 * i], qs[lane + 32 * i], p);
        p = warp_sum(p);
        if (lane == 0) sc[s] = clip5(p * INV_SD);
    }
    __syncthreads();

    float v = (t < 64) ? sc[t] : -1e30f;
    float m = warp_max(v);
    if (lane == 0) sh[warp] = m;
    __syncthreads();
    m = fmaxf(fmaxf(sh[0], sh[1]), fmaxf(sh[2], sh[3]));
    __syncthreads();
    float ex = (t < 64) ? expf(v - m) : 0.f;
    float s1 = warp_sum(ex);
    if (lane == 0) sh[warp] = s1;
    __syncthreads();
    const float inv = 1.f / (sh[0] + sh[1] + sh[2] + sh[3]);
    if (t < 64) sc[t] = ex * inv;
    __syncthreads();

    float acc[4];
    #pragma unroll
    for (int i = 0; i < 4; ++i) acc[i] = qs[t + 128 * i];
    for (int s = 0; s < 64; ++s) {
        const float w = sc[s];
        const float* vr = kbase + (size_t)s * 512;
        #pragma unroll
        for (int i = 0; i < 4; ++i) acc[i] = fmaf(w, vr[t + 128 * i], acc[i]);
    }
    float* xo = g_xin + ((size_t)e * L_ + l) * 512;
    #pragma unroll
    for (int i = 0; i < 4; ++i) xo[t + 128 * i] = acc[i];
}

// ---------------------------------------------------------------------------
// Multi-head self-attention over L=64, H=8, DH=64
// ---------------------------------------------------------------------------
__global__ void __launch_bounds__(256)
mha_kernel()
{
    const int e = blockIdx.x >> 3, h = blockIdx.x & 7;
    __shared__ float Kh[64][64];
    __shared__ float Vh[64][64];
    __shared__ float Pr[8][64];
    const float* qkv = g_qkvb + (size_t)e * L_ * 1536;
    const int tid = threadIdx.x, lane = tid & 31, warp = tid >> 5;

    for (int i = tid; i < 4096; i += 256) {
        const int m = i >> 6, d = i & 63;
        Kh[m][d] = qkv[m * 1536 +  512 + h * 64 + d];
        Vh[m][d] = qkv[m * 1536 + 1024 + h * 64 + d];
    }
    __syncthreads();

    for (int l = warp; l < 64; l += 8) {
        const float q0 = qkv[l * 1536 + h * 64 + lane];
        const float q1 = qkv[l * 1536 + h * 64 + lane + 32];
        float s0 = 0.f, s1 = 0.f;
        float mx = -1e30f;
        for (int m = 0; m < 64; ++m) {
            float p = q0 * Kh[m][lane] + q1 * Kh[m][lane + 32];
            p = warp_sum(p) * 0.125f;
            if (m == lane)      s0 = p;
            if (m == lane + 32) s1 = p;
            mx = fmaxf(mx, p);
        }
        const float e0 = expf(s0 - mx), e1 = expf(s1 - mx);
        const float tot = warp_sum(e0 + e1);
        const float inv = 1.f / tot;
        Pr[warp][lane]      = e0 * inv;
        Pr[warp][lane + 32] = e1 * inv;
        __syncwarp();
        float o0 = 0.f, o1 = 0.f;
        for (int m = 0; m < 64; ++m) {
            const float w = Pr[warp][m];
            o0 = fmaf(w, Vh[m][lane],      o0);
            o1 = fmaf(w, Vh[m][lane + 32], o1);
        }
        float* op = g_ao + ((size_t)e * L_ + l) * 512 + h * 64;
        op[lane]      = o0;
        op[lane + 32] = o1;
        __syncwarp();
    }
}

// ---------------------------------------------------------------------------
// Hierarchical memory retrieval
// ---------------------------------------------------------------------------
__global__ void __launch_bounds__(128)
memattn_kernel(const float* __restrict__ mem)
{
    __shared__ float es[512];
    __shared__ float sc[32];
    const int e = blockIdx.x >> 6, l = blockIdx.x & 63;
    const int t = threadIdx.x, lane = t & 31, warp = t >> 5;

    const float* erow = g_eo + ((size_t)e * L_ + l) * 512;
    #pragma unroll
    for (int i = t; i < 512; i += 128) es[i] = erow[i];
    __syncthreads();

    float racc[8];
    #pragma unroll
    for (int i = 0; i < 8; ++i) racc[i] = 0.f;

    for (int m = 0; m < 2; ++m) {
        const float* mb = mem + (size_t)m * KK_ * 512;
        for (int k = warp; k < 32; k += 4) {
            const float* mr = mb + (size_t)k * 512;
            float p = 0.f;
            #pragma unroll
            for (int i = 0; i < 16; ++i) p = fmaf(mr[lane + 32 * i], es[lane + 32 * i], p);
            p = warp_sum(p);
            if (lane == 0) sc[k] = clip5(p * INV_SD);
        }
        __syncthreads();
        if (warp == 0) {
            float v = sc[lane];
            float mx = warp_max(v);
            float ex = expf(v - mx);
            float sm = warp_sum(ex);
            sc[lane] = ex / sm;
        }
        __syncthreads();
        for (int k = 0; k < 32; ++k) {
            const float w = sc[k];
            const float* mr = mb + (size_t)k * 512;
            #pragma unroll
            for (int i = 0; i < 4; ++i)
                racc[m * 4 + i] = fmaf(w, mr[t + 128 * i], racc[m * 4 + i]);
        }
        __syncthreads();
    }
    float* rp = g_retr + ((size_t)e * L_ + l) * 1024;
    #pragma unroll
    for (int m = 0; m < 2; ++m)
        #pragma unroll
        for (int i = 0; i < 4; ++i)
            rp[m * 512 + t + 128 * i] = racc[m * 4 + i];
}

// ---------------------------------------------------------------------------
// Gating + fusion
// ---------------------------------------------------------------------------
__global__ void __launch_bounds__(512)
pooled_kernel()
{
    const int e = blockIdx.x, d = threadIdx.x;
    float s = 0.f;
    for (int l = 0; l < 64; ++l) s += g_eout[((size_t)e * L_ + l) * 512 + d];
    g_pooled[e * 512 + d] = s * (1.f / 64.f);
}

__global__ void __launch_bounds__(128)
gate_kernel(const float* __restrict__ gate, float* __restrict__ out_gw)
{
    __shared__ float sh[4];
    __shared__ float lg[4];
    const int t = threadIdx.x;
    for (int e = 0; e < 4; ++e) {
        float p = 0.f;
        for (int i = t; i < 512; i += 128) p += g_pooled[e * 512 + i] * gate[i];
        p = block_sum128(p, sh);
        if (t == 0) lg[e] = clip5(p);
    }
    __syncthreads();
    if (t == 0) {
        float mx = fmaxf(fmaxf(lg[0], lg[1]), fmaxf(lg[2], lg[3]));
        float ex[4], s = 0.f;
        #pragma unroll
        for (int e = 0; e < 4; ++e) { ex[e] = expf(lg[e] - mx); s += ex[e]; }
        #pragma unroll
        for (int e = 0; e < 4; ++e) {
            const float w = ex[e] / s;
            g_gw[e] = w;
            if (out_gw) out_gw[e] = w;
        }
    }
}

__global__ void __launch_bounds__(256)
fused_kernel(float* __restrict__ out)
{
    const int idx = blockIdx.x * 256 + threadIdx.x;
    if (idx < L_ * D_) {
        float s = 0.f;
        #pragma unroll
        for (int e = 0; e < 4; ++e) s = fmaf(g_gw[e], g_eout[(size_t)e * L_ * D_ + idx], s);
        out[idx] = s;
    }
}

// ---------------------------------------------------------------------------
// Host launcher
// ---------------------------------------------------------------------------
extern "C" void kernel_launch(void* const* d_in, const int* in_sizes, int n_in,
                              void* d_out, int out_size)
{
    const float* x          = (const float*)d_in[0];
    const float* al_w1      = (const float*)d_in[1];
    const float* al_b1      = (const float*)d_in[2];
    const float* al_w2      = (const float*)d_in[3];
    const float* al_b2      = (const float*)d_in[4];
    const float* al_g       = (const float*)d_in[5];
    const float* al_bt      = (const float*)d_in[6];
    const float* z          = (const float*)d_in[7];
    const float* wq         = (const float*)d_in[8];
    const float* wk         = (const float*)d_in[9];
    const float* wv         = (const float*)d_in[10];
    const float* wo         = (const float*)d_in[11];
    const float* bo         = (const float*)d_in[12];
    const float* attn_in_w  = (const float*)d_in[13];
    const float* attn_in_b  = (const float*)d_in[14];
    const float* attn_out_w = (const float*)d_in[15];
    const float* attn_out_b = (const float*)d_in[16];
    const float* ln1_g      = (const float*)d_in[17];
    const float* ln1_b      = (const float*)d_in[18];
    const float* ff_w1      = (const float*)d_in[19];
    const float* ff_b1      = (const float*)d_in[20];
    const float* ff_w2      = (const float*)d_in[21];
    const float* ff_b2      = (const float*)d_in[22];
    const float* ln2_g      = (const float*)d_in[23];
    const float* ln2_b      = (const float*)d_in[24];
    const float* memories   = (const float*)d_in[25];
    const float* mem_agg_w  = (const float*)d_in[26];
    const float* mem_agg_b  = (const float*)d_in[27];
    const float* ggate      = (const float*)d_in[28];
    (void)in_sizes; (void)n_in;

    float *KVb, *q, *zo, *tok, *tn, *xin, *qkvb, *ao, *aop,
          *x1, *ffh, *ffo, *eo, *retr, *eout;
    __half *xh, *h1h, *fh, *w1h, *w2h, *wkvh;
    cudaGetSymbolAddress((void**)&KVb,  g_KVb);
    cudaGetSymbolAddress((void**)&q,    g_q);
    cudaGetSymbolAddress((void**)&zo,   g_zo);
    cudaGetSymbolAddress((void**)&tok,  g_tok);
    cudaGetSymbolAddress((void**)&tn,   g_tn);
    cudaGetSymbolAddress((void**)&xin,  g_xin);
    cudaGetSymbolAddress((void**)&qkvb, g_qkvb);
    cudaGetSymbolAddress((void**)&ao,   g_ao);
    cudaGetSymbolAddress((void**)&aop,  g_aop);
    cudaGetSymbolAddress((void**)&x1,   g_x1);
    cudaGetSymbolAddress((void**)&ffh,  g_ffh);
    cudaGetSymbolAddress((void**)&ffo,  g_ffo);
    cudaGetSymbolAddress((void**)&eo,   g_eo);
    cudaGetSymbolAddress((void**)&retr, g_retr);
    cudaGetSymbolAddress((void**)&eout, g_eout);
    cudaGetSymbolAddress((void**)&xh,   g_xh);
    cudaGetSymbolAddress((void**)&h1h,  g_h1h);
    cudaGetSymbolAddress((void**)&fh,   g_fh);
    cudaGetSymbolAddress((void**)&w1h,  g_w1h);
    cudaGetSymbolAddress((void**)&w2h,  g_w2h);
    cudaGetSymbolAddress((void**)&wkvh, g_wkvh);

    cudaFuncSetAttribute(mma_gemm<true,  true,  true >, cudaFuncAttributeMaxDynamicSharedMemorySize, GEMM_SMEM_BYTES);
    cudaFuncSetAttribute(mma_gemm<false, false, false>, cudaFuncAttributeMaxDynamicSharedMemorySize, GEMM_SMEM_BYTES);
    cudaFuncSetAttribute(gemm2_ln_kernel, cudaFuncAttributeMaxDynamicSharedMemorySize, G2_SMEM_BYTES);

    float* out = (float*)d_out;

    // ---- operand prep (grid-stride) ----
    tohalf_kernel<<<1184, 256>>>(x, xh, E_*N_*DIN_/4);
    tohalf_kernel<<<592, 256>>>(al_w1, w1h, E_*DIN_*HID_/4);
    tohalf_kernel<<<592, 256>>>(al_w2, w2h, E_*HID_*D_/4);
    pack_kv_h<<<592, 256>>>(wk, wv, wkvh);

    // ---- Aligner ----
    mma_gemm<true, true, true><<<dim3(HID_/128, N_/128, E_), 512, GEMM_SMEM_BYTES>>>(
        xh, w1h, al_b1, nullptr, h1h, N_, HID_, DIN_);
    gemm2_ln_kernel<<<dim3(N_/32, 1, E_), 512, G2_SMEM_BYTES>>>(
        h1h, w2h, al_b2, al_g, al_bt);

    // ---- LSTCWA fused K|V GEMM (tensor cores, N=1024) ----
    mma_gemm<false, false, false><<<dim3(2*D_/128, N_/128, E_), 512, GEMM_SMEM_BYTES>>>(
        fh, wkvh, nullptr, KVb, nullptr, N_, 2*D_, D_);

    small_gemm_kernel<false, false, false><<<dim3(D_/64, 1, E_), 256>>>(
        z, wq, nullptr, nullptr, q, D_, D_,
        (long long)L_*D_, (long long)D_*D_, 0, (long long)L_*D_);
    lstcwa_kernel<<<E_ * L_, 128>>>();
    small_gemm_kernel<false, true, false><<<dim3(D_/64, 1, E_), 256>>>(
        zo, wo, bo, nullptr, tok, D_, D_,
        (long long)L_*D_, (long long)D_*D_, (long long)D_, (long long)L_*D_);

    // ---- Hierarchical MoE ----
    ln_kernel<false, false><<<E_ * L_, 128>>>(tok, nullptr, nullptr, nullptr, tn, L_);
    crossattn_kernel<<<E_ * L_, 128>>>();
    small_gemm_kernel<false, true, false><<<dim3(3*D_/64, 1, E_), 256>>>(
        xin, attn_in_w, attn_in_b, nullptr, qkvb, 3*D_, D_,
        (long long)L_*D_, (long long)D_*3*D_, (long long)3*D_, (long long)L_*3*D_);
    mha_kernel<<<E_ * H_, 256>>>();
    small_gemm_kernel<false, true, false><<<dim3(D_/64, 1, E_), 256>>>(
        ao, attn_out_w, attn_out_b, nullptr, aop, D_, D_,
        (long long)L_*D_, (long long)D_*D_, (long long)D_, (long long)L_*D_);
    ln_kernel<true, true><<<E_ * L_, 128>>>(aop, xin, ln1_g, ln1_b, x1, L_);
    small_gemm_kernel<true, true, false><<<dim3(FF_/64, 1, E_), 256>>>(
        x1, ff_w1, ff_b1, nullptr, ffh, FF_, D_,
        (long long)L_*D_, (long long)D_*FF_, (long long)FF_, (long long)L_*FF_);
    small_gemm_kernel<false, true, false><<<dim3(D_/64, 1, E_), 256>>>(
        ffh, ff_w2, ff_b2, nullptr, ffo, D_, FF_,
        (long long)L_*FF_, (long long)FF_*D_, (long long)D_, (long long)L_*D_);
    ln_kernel<true, true><<<E_ * L_, 128>>>(ffo, x1, ln2_g, ln2_b, eo, L_);

    // ---- Memory retrieval + aggregation ----
    memattn_kernel<<<E_ * L_, 128>>>(memories);
    small_gemm_kernel<false, true, true><<<dim3(D_/64, 1, E_), 256>>>(
        retr, mem_agg_w, mem_agg_b, eo, eout, D_, M_*D_,
        (long long)L_*M_*D_, 0, 0, (long long)L_*D_);

    // ---- Gating fusion ----
    pooled_kernel<<<E_, 512>>>();
    float* gw_out = (out_size >= L_ * D_ + E_) ? (out + L_ * D_) : nullptr;
    gate_kernel<<<1, 128>>>(ggate, gw_out);
    fused_kernel<<<(L_ * D_ + 255)/256, 256>>>(out);
}

// round 11
// speedup vs baseline: 1.0789x; 1.0789x over previous
#include <cuda_runtime.h>
#include <cuda_bf16.h>
#include <cuda_fp16.h>
#include <math.h>
#include <stdint.h>

// ---------------------------------------------------------------------------
// Problem constants
// ---------------------------------------------------------------------------
#define E_   4
#define N_   8192
#define DIN_ 1024
#define D_   512
#define L_   64
#define S_   128          // N_/L_
#define HID_ 1024
#define FF_  2048
#define M_   2
#define KK_  32
#define H_   8
#define DH_  64

#define INV_SD 0.04419417382415922f   // 1/sqrt(512)

// ---------------------------------------------------------------------------
// Scratch (static __device__ arrays; no allocation allowed)
// ---------------------------------------------------------------------------
static __device__ __align__(16) float g_F  [(size_t)E_*N_*D_];      // aligner out y (fp32)
static __device__ __align__(16) float g_KVb[(size_t)E_*N_*2*D_];    // fused [K|V], row stride 1024

// fp16 operand buffers
static __device__ __align__(16) __half g_xh [(size_t)E_*N_*DIN_];
static __device__ __align__(16) __half g_h1h[(size_t)E_*N_*HID_];
static __device__ __align__(16) __half g_fh [(size_t)E_*N_*D_];
static __device__ __align__(16) __half g_w1h[E_*DIN_*HID_];
static __device__ __align__(16) __half g_w2h[E_*HID_*D_];
static __device__ __align__(16) __half g_wkvh[E_*D_*2*D_];  // [K rows][2D cols]

static __device__ float g_q  [E_*L_*D_];
static __device__ float g_zo [E_*L_*D_];
static __device__ float g_tok[E_*L_*D_];
static __device__ float g_tn [E_*L_*D_];
static __device__ float g_xin[E_*L_*D_];
static __device__ float g_qkvb[E_*L_*3*D_];
static __device__ float g_ao [E_*L_*D_];
static __device__ float g_aop[E_*L_*D_];
static __device__ float g_x1 [E_*L_*D_];
static __device__ float g_ffh[E_*L_*FF_];
static __device__ float g_ffo[E_*L_*D_];
static __device__ float g_eo [E_*L_*D_];
static __device__ float g_retr[E_*L_*M_*D_];
static __device__ float g_eout[E_*L_*D_];
static __device__ float g_pooled[E_*D_];
static __device__ float g_gw[E_];

// ---------------------------------------------------------------------------
// Reduction helpers
// ---------------------------------------------------------------------------
__device__ __forceinline__ float warp_sum(float v) {
    #pragma unroll
    for (int o = 16; o; o >>= 1) v += __shfl_xor_sync(0xffffffffu, v, o);
    return v;
}
__device__ __forceinline__ float warp_max(float v) {
    #pragma unroll
    for (int o = 16; o; o >>= 1) v = fmaxf(v, __shfl_xor_sync(0xffffffffu, v, o));
    return v;
}
__device__ __forceinline__ float block_sum128(float v, float* sh) {
    int lane = threadIdx.x & 31, w = threadIdx.x >> 5;
    v = warp_sum(v);
    if (lane == 0) sh[w] = v;
    __syncthreads();
    float r = sh[0] + sh[1] + sh[2] + sh[3];
    __syncthreads();
    return r;
}
__device__ __forceinline__ float clip5(float x) {
    return fminf(fmaxf(x, -5.0f), 5.0f);
}

// ---------------------------------------------------------------------------
// Tensor-core primitives (legacy mma.sync path — tcgen05 unavailable at the
// harness's ptxas target sm_100)
// ---------------------------------------------------------------------------
__device__ __forceinline__ uint32_t smem_u32(const void* p) {
    return (uint32_t)__cvta_generic_to_shared(p);
}
__device__ __forceinline__ void cpa16(void* dst, const void* src) {
    uint32_t d = smem_u32(dst);
    asm volatile("cp.async.cg.shared.global [%0], [%1], 16;\n" :: "r"(d), "l"(src));
}
__device__ __forceinline__ void ldsm4(uint32_t* r, uint32_t addr) {
    asm volatile("ldmatrix.sync.aligned.m8n8.x4.shared.b16 {%0,%1,%2,%3}, [%4];\n"
                 : "=r"(r[0]), "=r"(r[1]), "=r"(r[2]), "=r"(r[3]) : "r"(addr));
}
__device__ __forceinline__ void ldsm4t(uint32_t* r, uint32_t addr) {
    asm volatile("ldmatrix.sync.aligned.m8n8.x4.trans.shared.b16 {%0,%1,%2,%3}, [%4];\n"
                 : "=r"(r[0]), "=r"(r[1]), "=r"(r[2]), "=r"(r[3]) : "r"(addr));
}
__device__ __forceinline__ void mma16816h(float* c, const uint32_t* a, const uint32_t* b) {
    asm volatile(
        "mma.sync.aligned.m16n8k16.row.col.f32.f16.f16.f32 "
        "{%0,%1,%2,%3}, {%4,%5,%6,%7}, {%8,%9}, {%0,%1,%2,%3};\n"
        : "+f"(c[0]), "+f"(c[1]), "+f"(c[2]), "+f"(c[3])
        : "r"(a[0]), "r"(a[1]), "r"(a[2]), "r"(a[3]), "r"(b[0]), "r"(b[1]));
}

// smem geometry: A fp16 (128x32, stride 40), B fp16 (32x128, stride 136)
#define A_STRIDE 40
#define B_STRIDE 136
#define SA_ELEMS (128 * A_STRIDE)       // 5120
#define SB_ELEMS (32 * B_STRIDE)        // 4352
#define STAGE_ELEMS (SA_ELEMS + SB_ELEMS)           // 9472 half
#define STAGES 4
#define GEMM_SMEM_BYTES (STAGES * STAGE_ELEMS * 2)  // 75776 B

__device__ __forceinline__ void gemm_prefetch(
    __half* s,
    const __half* __restrict__ A, const __half* __restrict__ B,
    int m0, int n0, int k0, int Ktot, int Ntot, int tid)
{
    __half* sA = s;
    __half* sB = s + SA_ELEMS;
    const int ar = tid >> 2, akc = (tid & 3) * 8;
    cpa16(sA + ar * A_STRIDE + akc, A + (size_t)(m0 + ar) * Ktot + k0 + akc);
    const int br = tid >> 4, bnc = (tid & 15) * 8;
    cpa16(sB + br * B_STRIDE + bnc, B + (size_t)(k0 + br) * Ntot + n0 + bnc);
}

// C[e] = act(A[e] @ B[e] + bias[e]); A,B fp16, fp32 accumulate.
// BM=BN=128, BK=32, 512 threads (16 warps, 4x4 grid, warp tile 32x32).
template<bool RELU, bool HAS_BIAS, bool OUT_HALF>
__global__ void __launch_bounds__(512, 1)
mma_gemm(const __half* __restrict__ A, const __half* __restrict__ B,
         const float* __restrict__ bias,
         float* __restrict__ Cf, __half* __restrict__ Ch,
         int Mtot, int Ntot, int Ktot)
{
    extern __shared__ __half sm[];
    const int e = blockIdx.z;
    A += (size_t)e * Mtot * Ktot;
    B += (size_t)e * Ktot * Ntot;
    if (HAS_BIAS) bias += (size_t)e * Ntot;
    if (OUT_HALF) Ch += (size_t)e * Mtot * Ntot;
    else          Cf += (size_t)e * Mtot * Ntot;

    const int m0 = blockIdx.y * 128, n0 = blockIdx.x * 128;
    const int tid = threadIdx.x, lane = tid & 31, warp = tid >> 5;
    const int wm = warp & 3, wn = warp >> 2;

    float acc[2][4][4];
    #pragma unroll
    for (int mi = 0; mi < 2; ++mi)
        #pragma unroll
        for (int ni = 0; ni < 4; ++ni)
            #pragma unroll
            for (int r = 0; r < 4; ++r) acc[mi][ni][r] = 0.f;

    const int nk = Ktot / 32;

    #pragma unroll
    for (int s = 0; s < STAGES - 1; ++s) {
        if (s < nk)
            gemm_prefetch(sm + s * STAGE_ELEMS, A, B, m0, n0, s * 32, Ktot, Ntot, tid);
        asm volatile("cp.async.commit_group;\n" ::: "memory");
    }

    for (int kt = 0; kt < nk; ++kt) {
        asm volatile("cp.async.wait_group %0;\n" :: "n"(STAGES - 2) : "memory");
        __syncthreads();

        const int pf = kt + STAGES - 1;
        if (pf < nk)
            gemm_prefetch(sm + (pf % STAGES) * STAGE_ELEMS, A, B,
                          m0, n0, pf * 32, Ktot, Ntot, tid);
        asm volatile("cp.async.commit_group;\n" ::: "memory");

        const __half* s = sm + (kt % STAGES) * STAGE_ELEMS;
        const uint32_t sbase = smem_u32(s);
        const uint32_t aB = sbase + (uint32_t)(((wm * 32 + (lane & 15)) * A_STRIDE
                                               + (lane >> 4) * 8) * 2);
        const uint32_t bB = sbase + (uint32_t)((SA_ELEMS
                            + ((lane & 7) + ((lane >> 3) & 1) * 8) * B_STRIDE
                            + wn * 32 + (lane >> 4) * 8) * 2);

        #pragma unroll
        for (int ks = 0; ks < 2; ++ks) {
            uint32_t a[2][4], b[4][2];
            #pragma unroll
            for (int mi = 0; mi < 2; ++mi)
                ldsm4(a[mi], aB + ks * 32 + mi * (16 * A_STRIDE * 2));
            #pragma unroll
            for (int pr = 0; pr < 2; ++pr) {
                uint32_t r[4];
                ldsm4t(r, bB + ks * (16 * B_STRIDE * 2) + pr * 32);
                b[2*pr][0] = r[0]; b[2*pr][1] = r[1];
                b[2*pr+1][0] = r[2]; b[2*pr+1][1] = r[3];
            }
            #pragma unroll
            for (int mi = 0; mi < 2; ++mi)
                #pragma unroll
                for (int ni = 0; ni < 4; ++ni)
                    mma16816h(acc[mi][ni], a[mi], b[ni]);
        }
    }

    const int g  = lane >> 2;
    const int c2 = (lane & 3) * 2;
    #pragma unroll
    for (int mi = 0; mi < 2; ++mi) {
        const int r0 = m0 + wm * 32 + mi * 16 + g;
        #pragma unroll
        for (int ni = 0; ni < 4; ++ni) {
            const int col = n0 + wn * 32 + ni * 8 + c2;
            float bx = 0.f, by = 0.f;
            if (HAS_BIAS) { float2 bb = *(const float2*)&bias[col]; bx = bb.x; by = bb.y; }
            float v00 = acc[mi][ni][0] + bx, v01 = acc[mi][ni][1] + by;
            float v10 = acc[mi][ni][2] + bx, v11 = acc[mi][ni][3] + by;
            if (RELU) {
                v00 = fmaxf(v00, 0.f); v01 = fmaxf(v01, 0.f);
                v10 = fmaxf(v10, 0.f); v11 = fmaxf(v11, 0.f);
            }
            if (OUT_HALF) {
                __half2 h0; h0.x = __float2half_rn(v00); h0.y = __float2half_rn(v01);
                __half2 h1; h1.x = __float2half_rn(v10); h1.y = __float2half_rn(v11);
                *(__half2*)(Ch + (size_t)r0 * Ntot + col)       = h0;
                *(__half2*)(Ch + (size_t)(r0 + 8) * Ntot + col) = h1;
            } else {
                float2 o0; o0.x = v00; o0.y = v01;
                float2 o1; o1.x = v10; o1.y = v11;
                *(float2*)&Cf[(size_t)r0 * Ntot + col]       = o0;
                *(float2*)&Cf[(size_t)(r0 + 8) * Ntot + col] = o1;
            }
        }
    }
}

// fp32 -> fp16 (one float4 per thread)
__global__ void __launch_bounds__(256)
tohalf_kernel(const float* __restrict__ in, __half* __restrict__ out, int n4)
{
    const int i = blockIdx.x * 256 + threadIdx.x;
    if (i >= n4) return;
    const float4 v = ((const float4*)in)[i];
    __half2 h0, h1;
    h0.x = __float2half_rn(v.x); h0.y = __float2half_rn(v.y);
    h1.x = __float2half_rn(v.z); h1.y = __float2half_rn(v.w);
    __half2* op = (__half2*)(out + 4 * (size_t)i);
    op[0] = h0; op[1] = h1;
}

// pack wk|wv -> [E][D rows (k)][1024 cols] fp16
__global__ void __launch_bounds__(256)
pack_kv_h(const float* __restrict__ wk, const float* __restrict__ wv,
          __half* __restrict__ out)
{
    const int i = blockIdx.x * 256 + threadIdx.x;   // over E*D*2D/4
    if (i >= E_ * D_ * 2 * D_ / 4) return;
    const int idx4 = i * 4;
    const int e   = idx4 / (D_ * 2 * D_);
    const int rem = idx4 % (D_ * 2 * D_);
    const int r   = rem / (2 * D_);
    const int c   = rem % (2 * D_);
    const float* src = (c < D_)
        ? (wk + ((size_t)e * D_ + r) * D_ + c)
        : (wv + ((size_t)e * D_ + r) * D_ + (c - D_));
    const float4 v = *(const float4*)src;
    __half2 h0, h1;
    h0.x = __float2half_rn(v.x); h0.y = __float2half_rn(v.y);
    h1.x = __float2half_rn(v.z); h1.y = __float2half_rn(v.w);
    __half2* op = (__half2*)(out + idx4);
    op[0] = h0; op[1] = h1;
}

// ---------------------------------------------------------------------------
// Small GEMM: M=64 rows, 64-wide N tiles, BK=16, 256 thr, 4x4 per thread
// ---------------------------------------------------------------------------
template<bool RELU, bool HAS_BIAS, bool RESID>
__global__ void __launch_bounds__(256)
small_gemm_kernel(const float* __restrict__ A, const float* __restrict__ B,
                  const float* __restrict__ bias, const float* __restrict__ resid,
                  float* __restrict__ C, int Ntot, int Ktot,
                  long long sA, long long sB, long long sBias, long long sC)
{
    const int e = blockIdx.z;
    A += (size_t)e * sA;
    B += (size_t)e * sB;
    C += (size_t)e * sC;
    if (HAS_BIAS) bias += (size_t)e * sBias;
    if (RESID)    resid += (size_t)e * sC;

    __shared__ float As[16][64];
    __shared__ float Bs[16][68];

    const int tid   = threadIdx.x;
    const int n0    = blockIdx.x * 64;
    const int arow  = tid >> 2;
    const int acol4 = (tid & 3) * 4;
    const int brow  = tid >> 4;
    const int bcol4 = (tid & 15) * 4;
    const int tr    = (tid >> 4) * 4;
    const int tc    = (tid & 15) * 4;

    float acc[4][4];
    #pragma unroll
    for (int i = 0; i < 4; i++)
        #pragma unroll
        for (int j = 0; j < 4; j++) acc[i][j] = 0.f;

    const float* Ap = A + (size_t)arow * Ktot + acol4;
    const float* Bp = B + (size_t)brow * Ntot + n0 + bcol4;

    for (int k0 = 0; k0 < Ktot; k0 += 16) {
        float4 a4 = *(const float4*)Ap;
        float4 b4 = *(const float4*)Bp;
        As[acol4 + 0][arow] = a4.x;
        As[acol4 + 1][arow] = a4.y;
        As[acol4 + 2][arow] = a4.z;
        As[acol4 + 3][arow] = a4.w;
        *(float4*)&Bs[brow][bcol4] = b4;
        __syncthreads();
        #pragma unroll
        for (int k = 0; k < 16; ++k) {
            float ar[4], br[4];
            #pragma unroll
            for (int i = 0; i < 4; ++i) ar[i] = As[k][tr + i];
            #pragma unroll
            for (int j = 0; j < 4; ++j) br[j] = Bs[k][tc + j];
            #pragma unroll
            for (int i = 0; i < 4; ++i)
                #pragma unroll
                for (int j = 0; j < 4; ++j)
                    acc[i][j] = fmaf(ar[i], br[j], acc[i][j]);
        }
        __syncthreads();
        Ap += 16;
        Bp += (size_t)16 * Ntot;
    }

    #pragma unroll
    for (int i = 0; i < 4; ++i) {
        const int row = tr + i;
        float* cp = C + (size_t)row * Ntot + n0 + tc;
        #pragma unroll
        for (int j = 0; j < 4; ++j) {
            float o = acc[i][j];
            if (HAS_BIAS) o += bias[n0 + tc + j];
            if (RESID)    o += resid[(size_t)row * Ntot + n0 + tc + j];
            if (RELU)     o = fmaxf(o, 0.f);
            cp[j] = o;
        }
    }
}

// ---------------------------------------------------------------------------
// LayerNorm over D=512, 128 threads/row: out = LN(in [+ res]) [* g + b]
// ---------------------------------------------------------------------------
template<bool RES, bool AFF>
__global__ void __launch_bounds__(128)
ln_kernel(const float* __restrict__ in, const float* __restrict__ res,
          const float* __restrict__ gg, const float* __restrict__ bb,
          float* __restrict__ out, int rowsPerE)
{
    __shared__ float sh[4];
    const int row = blockIdx.x;
    const int e   = row / rowsPerE;
    const int t   = threadIdx.x;
    const float* ip = in + (size_t)row * 512;

    float v[4];
    #pragma unroll
    for (int i = 0; i < 4; ++i) {
        v[i] = ip[t + 128 * i];
        if (RES) v[i] += res[(size_t)row * 512 + t + 128 * i];
    }
    float s = block_sum128(v[0] + v[1] + v[2] + v[3], sh);
    const float mu = s * (1.f / 512.f);
    float q = 0.f;
    #pragma unroll
    for (int i = 0; i < 4; ++i) { float d = v[i] - mu; q += d * d; }
    q = block_sum128(q, sh);
    const float rs = rsqrtf(q * (1.f / 512.f) + 1e-5f);
    #pragma unroll
    for (int i = 0; i < 4; ++i) {
        float o = (v[i] - mu) * rs;
        if (AFF) o = o * gg[e * 512 + t + 128 * i] + bb[e * 512 + t + 128 * i];
        out[(size_t)row * 512 + t + 128 * i] = o;
    }
}

// Double LN for aligner output: f = LN( LN(y)*g + bt ); writes fp16
__global__ void __launch_bounds__(128)
ln_double_kernel(const float* __restrict__ gg, const float* __restrict__ bt)
{
    __shared__ float sh[4];
    const int row = blockIdx.x;           // 0 .. E*N-1
    const int e   = row / N_;
    const int t   = threadIdx.x;
    const float* ip = g_F + (size_t)row * 512;

    float v[4];
    #pragma unroll
    for (int i = 0; i < 4; ++i) v[i] = ip[t + 128 * i];
    float s = block_sum128(v[0] + v[1] + v[2] + v[3], sh);
    float mu = s * (1.f / 512.f);
    float q = 0.f;
    #pragma unroll
    for (int i = 0; i < 4; ++i) { float d = v[i] - mu; q += d * d; }
    q = block_sum128(q, sh);
    float rs = rsqrtf(q * (1.f / 512.f) + 1e-5f);
    #pragma unroll
    for (int i = 0; i < 4; ++i)
        v[i] = (v[i] - mu) * rs * gg[e * 512 + t + 128 * i] + bt[e * 512 + t + 128 * i];
    s = block_sum128(v[0] + v[1] + v[2] + v[3], sh);
    mu = s * (1.f / 512.f);
    q = 0.f;
    #pragma unroll
    for (int i = 0; i < 4; ++i) { float d = v[i] - mu; q += d * d; }
    q = block_sum128(q, sh);
    rs = rsqrtf(q * (1.f / 512.f) + 1e-5f);
    #pragma unroll
    for (int i = 0; i < 4; ++i)
        g_fh[(size_t)row * 512 + t + 128 * i] = __float2half_rn((v[i] - mu) * rs);
}

// ---------------------------------------------------------------------------
// LSTCWA segment cross-attention (256 threads/block for MLP; math order
// identical to the 128-thread version — bit-identical results)
// ---------------------------------------------------------------------------
__global__ void __launch_bounds__(256)
lstcwa_kernel()
{
    __shared__ float qs[512];
    __shared__ float sc[128];
    __shared__ float sh[8];
    const int e = blockIdx.x >> 6, l = blockIdx.x & 63;
    const int t = threadIdx.x, lane = t & 31, warp = t >> 5;

    const float* qrow = g_q + ((size_t)e * L_ + l) * 512;
    #pragma unroll
    for (int i = t; i < 512; i += 256) qs[i] = qrow[i];
    __syncthreads();

    const float* kvbase = g_KVb + ((size_t)e * N_ + (size_t)l * S_) * 1024;
    // scores: 8 warps over 128 rows
    for (int s = warp; s < 128; s += 8) {
        const float* kr = kvbase + (size_t)s * 1024;
        float p = 0.f;
        #pragma unroll
        for (int i = 0; i < 16; ++i) p = fmaf(kr[lane + 32 * i], qs[lane + 32 * i], p);
        p = warp_sum(p);
        if (lane == 0) sc[s] = clip5(p * INV_SD);
    }
    __syncthreads();

    // softmax over 128 scores (first 4 warps hold them)
    float v = (t < 128) ? sc[t] : -1e30f;
    float m = warp_max(v);
    if (lane == 0) sh[warp] = m;
    __syncthreads();
    m = fmaxf(fmaxf(sh[0], sh[1]), fmaxf(sh[2], sh[3]));
    __syncthreads();
    float ex = (t < 128) ? expf(v - m) : 0.f;
    float s1 = warp_sum(ex);
    if (lane == 0) sh[warp] = s1;
    __syncthreads();
    const float inv = 1.f / (sh[0] + sh[1] + sh[2] + sh[3]);
    if (t < 128) sc[t] = ex * inv;
    __syncthreads();

    // weighted V sum: 2 columns per thread (t, t+256); s-order unchanged
    const float* vbase = kvbase + 512;
    float acc[2] = {0.f, 0.f};
    for (int s = 0; s < 128; ++s) {
        const float w = sc[s];
        const float* vr = vbase + (size_t)s * 1024;
        acc[0] = fmaf(w, vr[t], acc[0]);
        acc[1] = fmaf(w, vr[t + 256], acc[1]);
    }
    float* zo = g_zo + ((size_t)e * L_ + l) * 512;
    zo[t]       = acc[0];
    zo[t + 256] = acc[1];
}

// ---------------------------------------------------------------------------
// Cross-backbone attention
// ---------------------------------------------------------------------------
__global__ void __launch_bounds__(128)
crossattn_kernel()
{
    __shared__ float qs[512];
    __shared__ float sc[64];
    __shared__ float sh[4];
    const int e = blockIdx.x >> 6, l = blockIdx.x & 63;
    const int ce = (e == 0) ? 1 : 0;
    const int t = threadIdx.x, lane = t & 31, warp = t >> 5;

    const float* qrow = g_tn + ((size_t)e * L_ + l) * 512;
    #pragma unroll
    for (int i = t; i < 512; i += 128) qs[i] = qrow[i];
    __syncthreads();

    const float* kbase = g_tn + (size_t)ce * L_ * 512;
    for (int s = warp; s < 64; s += 4) {
        const float* kr = kbase + (size_t)s * 512;
        float p = 0.f;
        #pragma unroll
        for (int i = 0; i < 16; ++i) p = fmaf(kr[lane + 32 * i], qs[lane + 32 * i], p);
        p = warp_sum(p);
        if (lane == 0) sc[s] = clip5(p * INV_SD);
    }
    __syncthreads();

    float v = (t < 64) ? sc[t] : -1e30f;
    float m = warp_max(v);
    if (lane == 0) sh[warp] = m;
    __syncthreads();
    m = fmaxf(fmaxf(sh[0], sh[1]), fmaxf(sh[2], sh[3]));
    __syncthreads();
    float ex = (t < 64) ? expf(v - m) : 0.f;
    float s1 = warp_sum(ex);
    if (lane == 0) sh[warp] = s1;
    __syncthreads();
    const float inv = 1.f / (sh[0] + sh[1] + sh[2] + sh[3]);
    if (t < 64) sc[t] = ex * inv;
    __syncthreads();

    float acc[4];
    #pragma unroll
    for (int i = 0; i < 4; ++i) acc[i] = qs[t + 128 * i];
    for (int s = 0; s < 64; ++s) {
        const float w = sc[s];
        const float* vr = kbase + (size_t)s * 512;
        #pragma unroll
        for (int i = 0; i < 4; ++i) acc[i] = fmaf(w, vr[t + 128 * i], acc[i]);
    }
    float* xo = g_xin + ((size_t)e * L_ + l) * 512;
    #pragma unroll
    for (int i = 0; i < 4; ++i) xo[t + 128 * i] = acc[i];
}

// ---------------------------------------------------------------------------
// Multi-head self-attention over L=64, H=8, DH=64
// ---------------------------------------------------------------------------
__global__ void __launch_bounds__(256)
mha_kernel()
{
    const int e = blockIdx.x >> 3, h = blockIdx.x & 7;
    __shared__ float Kh[64][64];
    __shared__ float Vh[64][64];
    __shared__ float Pr[8][64];
    const float* qkv = g_qkvb + (size_t)e * L_ * 1536;
    const int tid = threadIdx.x, lane = tid & 31, warp = tid >> 5;

    for (int i = tid; i < 4096; i += 256) {
        const int m = i >> 6, d = i & 63;
        Kh[m][d] = qkv[m * 1536 +  512 + h * 64 + d];
        Vh[m][d] = qkv[m * 1536 + 1024 + h * 64 + d];
    }
    __syncthreads();

    for (int l = warp; l < 64; l += 8) {
        const float q0 = qkv[l * 1536 + h * 64 + lane];
        const float q1 = qkv[l * 1536 + h * 64 + lane + 32];
        float s0 = 0.f, s1 = 0.f;
        float mx = -1e30f;
        for (int m = 0; m < 64; ++m) {
            float p = q0 * Kh[m][lane] + q1 * Kh[m][lane + 32];
            p = warp_sum(p) * 0.125f;
            if (m == lane)      s0 = p;
            if (m == lane + 32) s1 = p;
            mx = fmaxf(mx, p);
        }
        const float e0 = expf(s0 - mx), e1 = expf(s1 - mx);
        const float tot = warp_sum(e0 + e1);
        const float inv = 1.f / tot;
        Pr[warp][lane]      = e0 * inv;
        Pr[warp][lane + 32] = e1 * inv;
        __syncwarp();
        float o0 = 0.f, o1 = 0.f;
        for (int m = 0; m < 64; ++m) {
            const float w = Pr[warp][m];
            o0 = fmaf(w, Vh[m][lane],      o0);
            o1 = fmaf(w, Vh[m][lane + 32], o1);
        }
        float* op = g_ao + ((size_t)e * L_ + l) * 512 + h * 64;
        op[lane]      = o0;
        op[lane + 32] = o1;
        __syncwarp();
    }
}

// ---------------------------------------------------------------------------
// Hierarchical memory retrieval
// ---------------------------------------------------------------------------
__global__ void __launch_bounds__(128)
memattn_kernel(const float* __restrict__ mem)
{
    __shared__ float es[512];
    __shared__ float sc[32];
    const int e = blockIdx.x >> 6, l = blockIdx.x & 63;
    const int t = threadIdx.x, lane = t & 31, warp = t >> 5;

    const float* erow = g_eo + ((size_t)e * L_ + l) * 512;
    #pragma unroll
    for (int i = t; i < 512; i += 128) es[i] = erow[i];
    __syncthreads();

    float racc[8];
    #pragma unroll
    for (int i = 0; i < 8; ++i) racc[i] = 0.f;

    for (int m = 0; m < 2; ++m) {
        const float* mb = mem + (size_t)m * KK_ * 512;
        for (int k = warp; k < 32; k += 4) {
            const float* mr = mb + (size_t)k * 512;
            float p = 0.f;
            #pragma unroll
            for (int i = 0; i < 16; ++i) p = fmaf(mr[lane + 32 * i], es[lane + 32 * i], p);
            p = warp_sum(p);
            if (lane == 0) sc[k] = clip5(p * INV_SD);
        }
        __syncthreads();
        if (warp == 0) {
            float v = sc[lane];
            float mx = warp_max(v);
            float ex = expf(v - mx);
            float sm = warp_sum(ex);
            sc[lane] = ex / sm;
        }
        __syncthreads();
        for (int k = 0; k < 32; ++k) {
            const float w = sc[k];
            const float* mr = mb + (size_t)k * 512;
            #pragma unroll
            for (int i = 0; i < 4; ++i)
                racc[m * 4 + i] = fmaf(w, mr[t + 128 * i], racc[m * 4 + i]);
        }
        __syncthreads();
    }
    float* rp = g_retr + ((size_t)e * L_ + l) * 1024;
    #pragma unroll
    for (int m = 0; m < 2; ++m)
        #pragma unroll
        for (int i = 0; i < 4; ++i)
            rp[m * 512 + t + 128 * i] = racc[m * 4 + i];
}

// ---------------------------------------------------------------------------
// Gating + fusion
// ---------------------------------------------------------------------------
__global__ void __launch_bounds__(512)
pooled_kernel()
{
    const int e = blockIdx.x, d = threadIdx.x;
    float s = 0.f;
    for (int l = 0; l < 64; ++l) s += g_eout[((size_t)e * L_ + l) * 512 + d];
    g_pooled[e * 512 + d] = s * (1.f / 64.f);
}

__global__ void __launch_bounds__(128)
gate_kernel(const float* __restrict__ gate, float* __restrict__ out_gw)
{
    __shared__ float sh[4];
    __shared__ float lg[4];
    const int t = threadIdx.x;
    for (int e = 0; e < 4; ++e) {
        float p = 0.f;
        for (int i = t; i < 512; i += 128) p += g_pooled[e * 512 + i] * gate[i];
        p = block_sum128(p, sh);
        if (t == 0) lg[e] = clip5(p);
    }
    __syncthreads();
    if (t == 0) {
        float mx = fmaxf(fmaxf(lg[0], lg[1]), fmaxf(lg[2], lg[3]));
        float ex[4], s = 0.f;
        #pragma unroll
        for (int e = 0; e < 4; ++e) { ex[e] = expf(lg[e] - mx); s += ex[e]; }
        #pragma unroll
        for (int e = 0; e < 4; ++e) {
            const float w = ex[e] / s;
            g_gw[e] = w;
            if (out_gw) out_gw[e] = w;
        }
    }
}

__global__ void __launch_bounds__(256)
fused_kernel(float* __restrict__ out)
{
    const int idx = blockIdx.x * 256 + threadIdx.x;
    if (idx < L_ * D_) {
        float s = 0.f;
        #pragma unroll
        for (int e = 0; e < 4; ++e) s = fmaf(g_gw[e], g_eout[(size_t)e * L_ * D_ + idx], s);
        out[idx] = s;
    }
}

// ---------------------------------------------------------------------------
// Host launcher
// ---------------------------------------------------------------------------
extern "C" void kernel_launch(void* const* d_in, const int* in_sizes, int n_in,
                              void* d_out, int out_size)
{
    const float* x          = (const float*)d_in[0];
    const float* al_w1      = (const float*)d_in[1];
    const float* al_b1      = (const float*)d_in[2];
    const float* al_w2      = (const float*)d_in[3];
    const float* al_b2      = (const float*)d_in[4];
    const float* al_g       = (const float*)d_in[5];
    const float* al_bt      = (const float*)d_in[6];
    const float* z          = (const float*)d_in[7];
    const float* wq         = (const float*)d_in[8];
    const float* wk         = (const float*)d_in[9];
    const float* wv         = (const float*)d_in[10];
    const float* wo         = (const float*)d_in[11];
    const float* bo         = (const float*)d_in[12];
    const float* attn_in_w  = (const float*)d_in[13];
    const float* attn_in_b  = (const float*)d_in[14];
    const float* attn_out_w = (const float*)d_in[15];
    const float* attn_out_b = (const float*)d_in[16];
    const float* ln1_g      = (const float*)d_in[17];
    const float* ln1_b      = (const float*)d_in[18];
    const float* ff_w1      = (const float*)d_in[19];
    const float* ff_b1      = (const float*)d_in[20];
    const float* ff_w2      = (const float*)d_in[21];
    const float* ff_b2      = (const float*)d_in[22];
    const float* ln2_g      = (const float*)d_in[23];
    const float* ln2_b      = (const float*)d_in[24];
    const float* memories   = (const float*)d_in[25];
    const float* mem_agg_w  = (const float*)d_in[26];
    const float* mem_agg_b  = (const float*)d_in[27];
    const float* ggate      = (const float*)d_in[28];
    (void)in_sizes; (void)n_in;

    float *KVb, *q, *zo, *tok, *tn, *xin, *qkvb, *ao, *aop,
          *x1, *ffh, *ffo, *eo, *retr, *eout;
    __half *xh, *h1h, *fh, *w1h, *w2h, *wkvh;
    float *F;
    cudaGetSymbolAddress((void**)&F,    g_F);
    cudaGetSymbolAddress((void**)&KVb,  g_KVb);
    cudaGetSymbolAddress((void**)&q,    g_q);
    cudaGetSymbolAddress((void**)&zo,   g_zo);
    cudaGetSymbolAddress((void**)&tok,  g_tok);
    cudaGetSymbolAddress((void**)&tn,   g_tn);
    cudaGetSymbolAddress((void**)&xin,  g_xin);
    cudaGetSymbolAddress((void**)&qkvb, g_qkvb);
    cudaGetSymbolAddress((void**)&ao,   g_ao);
    cudaGetSymbolAddress((void**)&aop,  g_aop);
    cudaGetSymbolAddress((void**)&x1,   g_x1);
    cudaGetSymbolAddress((void**)&ffh,  g_ffh);
    cudaGetSymbolAddress((void**)&ffo,  g_ffo);
    cudaGetSymbolAddress((void**)&eo,   g_eo);
    cudaGetSymbolAddress((void**)&retr, g_retr);
    cudaGetSymbolAddress((void**)&eout, g_eout);
    cudaGetSymbolAddress((void**)&xh,   g_xh);
    cudaGetSymbolAddress((void**)&h1h,  g_h1h);
    cudaGetSymbolAddress((void**)&fh,   g_fh);
    cudaGetSymbolAddress((void**)&w1h,  g_w1h);
    cudaGetSymbolAddress((void**)&w2h,  g_w2h);
    cudaGetSymbolAddress((void**)&wkvh, g_wkvh);

    cudaFuncSetAttribute(mma_gemm<true,  true,  true >, cudaFuncAttributeMaxDynamicSharedMemorySize, GEMM_SMEM_BYTES);
    cudaFuncSetAttribute(mma_gemm<false, true,  false>, cudaFuncAttributeMaxDynamicSharedMemorySize, GEMM_SMEM_BYTES);
    cudaFuncSetAttribute(mma_gemm<false, false, false>, cudaFuncAttributeMaxDynamicSharedMemorySize, GEMM_SMEM_BYTES);

    float* out = (float*)d_out;

    // ---- operand prep ----
    tohalf_kernel<<<(E_*N_*DIN_/4 + 255)/256, 256>>>(x, xh, E_*N_*DIN_/4);
    tohalf_kernel<<<(E_*DIN_*HID_/4 + 255)/256, 256>>>(al_w1, w1h, E_*DIN_*HID_/4);
    tohalf_kernel<<<(E_*HID_*D_/4 + 255)/256, 256>>>(al_w2, w2h, E_*HID_*D_/4);
    pack_kv_h<<<(E_*D_*2*D_/4 + 255)/256, 256>>>(wk, wv, wkvh);

    // ---- Aligner (tensor cores, fp16 single-pass) ----
    mma_gemm<true, true, true><<<dim3(HID_/128, N_/128, E_), 512, GEMM_SMEM_BYTES>>>(
        xh, w1h, al_b1, nullptr, h1h, N_, HID_, DIN_);
    mma_gemm<false, true, false><<<dim3(D_/128, N_/128, E_), 512, GEMM_SMEM_BYTES>>>(
        h1h, w2h, al_b2, F, nullptr, N_, D_, HID_);
    ln_double_kernel<<<E_ * N_, 128>>>(al_g, al_bt);

    // ---- LSTCWA fused K|V GEMM (tensor cores, N=1024) ----
    mma_gemm<false, false, false><<<dim3(2*D_/128, N_/128, E_), 512, GEMM_SMEM_BYTES>>>(
        fh, wkvh, nullptr, KVb, nullptr, N_, 2*D_, D_);

    small_gemm_kernel<false, false, false><<<dim3(D_/64, 1, E_), 256>>>(
        z, wq, nullptr, nullptr, q, D_, D_,
        (long long)L_*D_, (long long)D_*D_, 0, (long long)L_*D_);
    lstcwa_kernel<<<E_ * L_, 256>>>();
    small_gemm_kernel<false, true, false><<<dim3(D_/64, 1, E_), 256>>>(
        zo, wo, bo, nullptr, tok, D_, D_,
        (long long)L_*D_, (long long)D_*D_, (long long)D_, (long long)L_*D_);

    // ---- Hierarchical MoE ----
    ln_kernel<false, false><<<E_ * L_, 128>>>(tok, nullptr, nullptr, nullptr, tn, L_);
    crossattn_kernel<<<E_ * L_, 128>>>();
    small_gemm_kernel<false, true, false><<<dim3(3*D_/64, 1, E_), 256>>>(
        xin, attn_in_w, attn_in_b, nullptr, qkvb, 3*D_, D_,
        (long long)L_*D_, (long long)D_*3*D_, (long long)3*D_, (long long)L_*3*D_);
    mha_kernel<<<E_ * H_, 256>>>();
    small_gemm_kernel<false, true, false><<<dim3(D_/64, 1, E_), 256>>>(
        ao, attn_out_w, attn_out_b, nullptr, aop, D_, D_,
        (long long)L_*D_, (long long)D_*D_, (long long)D_, (long long)L_*D_);
    ln_kernel<true, true><<<E_ * L_, 128>>>(aop, xin, ln1_g, ln1_b, x1, L_);
    small_gemm_kernel<true, true, false><<<dim3(FF_/64, 1, E_), 256>>>(
        x1, ff_w1, ff_b1, nullptr, ffh, FF_, D_,
        (long long)L_*D_, (long long)D_*FF_, (long long)FF_, (long long)L_*FF_);
    small_gemm_kernel<false, true, false><<<dim3(D_/64, 1, E_), 256>>>(
        ffh, ff_w2, ff_b2, nullptr, ffo, D_, FF_,
        (long long)L_*FF_, (long long)FF_*D_, (long long)D_, (long long)L_*D_);
    ln_kernel<true, true><<<E_ * L_, 128>>>(ffo, x1, ln2_g, ln2_b, eo, L_);

    // ---- Memory retrieval + aggregation ----
    memattn_kernel<<<E_ * L_, 128>>>(memories);
    small_gemm_kernel<false, true, true><<<dim3(D_/64, 1, E_), 256>>>(
        retr, mem_agg_w, mem_agg_b, eo, eout, D_, M_*D_,
        (long long)L_*M_*D_, 0, 0, (long long)L_*D_);

    // ---- Gating fusion ----
    pooled_kernel<<<E_, 512>>>();
    float* gw_out = (out_size >= L_ * D_ + E_) ? (out + L_ * D_) : nullptr;
    gate_kernel<<<1, 128>>>(ggate, gw_out);
    fused_kernel<<<(L_ * D_ + 255)/256, 256>>>(out);
}